// round 4
// baseline (speedup 1.0000x reference)
#include <cuda_runtime.h>
#include <math.h>

// Fixed shape: H=1024, B=64, T=1024
#define BB 64
#define TS 1024
#define HS 1024
#define TT 16                    // t per tile
#define NPAIRS 2048              // (b, 32t-pair) columns; pair = 2 tiles, same b
#define THREADS 512
#define GRID 148
#define HSTRIDE ((size_t)BB * TS)    // floats between consecutive h
#define L2E 1.44269504088896340736f

// Deterministic per-pair partials: [NPAIRS][H] = 8 MB
__device__ float g_partial[NPAIRS * HS];

struct Smem {
    float sA[TT][17];
    float sB[TT][17];
    float sC[TT][17];
    float sS[TT];
    float sM[TT];
    float sInv[TT];
};

// Issue 8 independent LDG.128 for tile (p, sub) into v[8].
// Thread covers h = h0..h0+7 (i), t = t0 + tg*4 + j (float4 lanes).
__device__ __forceinline__ void issue_tile(float4 v[8], const float* __restrict__ enc,
                                           int p, int sub, int h0, int tg) {
    const int b  = p >> 5;
    const int t0 = (p & 31) * 32 + sub * TT;
    const float* gp = enc + (size_t)h0 * HSTRIDE + (size_t)b * TS + t0 + tg * 4;
    #pragma unroll
    for (int i = 0; i < 8; ++i)
        v[i] = __ldg(reinterpret_cast<const float4*>(gp + (size_t)i * HSTRIDE));
}

// Full epilogue for one 16t x 1024h tile held in v (8 float4 per thread).
// Accumulates softmax-normalized values per-h into a[8].
__device__ __forceinline__ void process_tile(float4 v[8], const float dhv[8], float a[8],
                                             Smem& sm, int w, int l, int tg, int hcw) {
    // stats partials over this thread's 8 h
    float sp[4] = {0.f, 0.f, 0.f, 0.f};
    float mx[4] = {-INFINITY, -INFINITY, -INFINITY, -INFINITY};
    float mn[4] = { INFINITY,  INFINITY,  INFINITY,  INFINITY};
    #pragma unroll
    for (int i = 0; i < 8; ++i) {
        const float vv[4] = {v[i].x, v[i].y, v[i].z, v[i].w};
        #pragma unroll
        for (int j = 0; j < 4; ++j) {
            sp[j] = fmaf(vv[j], dhv[i], sp[j]);
            mx[j] = fmaxf(mx[j], vv[j]);
            mn[j] = fminf(mn[j], vv[j]);
        }
    }
    // reduce across the 8 h-chunks in the warp (lanes differing in hcw)
    #pragma unroll
    for (int off = 4; off <= 16; off <<= 1)
        #pragma unroll
        for (int j = 0; j < 4; ++j) {
            sp[j] += __shfl_xor_sync(0xffffffffu, sp[j], off);
            mx[j]  = fmaxf(mx[j], __shfl_xor_sync(0xffffffffu, mx[j], off));
            mn[j]  = fminf(mn[j], __shfl_xor_sync(0xffffffffu, mn[j], off));
        }
    if (hcw == 0) {
        #pragma unroll
        for (int j = 0; j < 4; ++j) {
            sm.sA[tg * 4 + j][w] = sp[j];
            sm.sB[tg * 4 + j][w] = mx[j];
            sm.sC[tg * 4 + j][w] = mn[j];
        }
    }
    __syncthreads();

    // warp w owns t = w: combine 16 warp-partials
    {
        float s = sm.sA[w][l & 15];
        float x = sm.sB[w][l & 15];
        float n = sm.sC[w][l & 15];
        #pragma unroll
        for (int off = 8; off; off >>= 1) {
            s += __shfl_xor_sync(0xffffffffu, s, off);
            x  = fmaxf(x, __shfl_xor_sync(0xffffffffu, x, off));
            n  = fminf(n, __shfl_xor_sync(0xffffffffu, n, off));
        }
        if (l == 0) {
            sm.sS[w] = s;
            sm.sM[w] = (s >= 0.0f) ? x * s : n * s;   // exact max_h(v*s)
        }
    }
    __syncthreads();

    // exp2 on registers + denominator (log2e folded into s, M)
    float st[4], Mt[4], ds[4] = {0.f, 0.f, 0.f, 0.f};
    #pragma unroll
    for (int j = 0; j < 4; ++j) {
        st[j] = sm.sS[tg * 4 + j] * L2E;
        Mt[j] = sm.sM[tg * 4 + j] * L2E;
    }
    #pragma unroll
    for (int i = 0; i < 8; ++i) {
        float vv[4] = {v[i].x, v[i].y, v[i].z, v[i].w};
        #pragma unroll
        for (int j = 0; j < 4; ++j) {
            vv[j] = exp2f(fmaf(vv[j], st[j], -Mt[j]));
            ds[j] += vv[j];
        }
        v[i].x = vv[0]; v[i].y = vv[1]; v[i].z = vv[2]; v[i].w = vv[3];
    }
    #pragma unroll
    for (int off = 4; off <= 16; off <<= 1)
        #pragma unroll
        for (int j = 0; j < 4; ++j)
            ds[j] += __shfl_xor_sync(0xffffffffu, ds[j], off);
    if (hcw == 0)
        #pragma unroll
        for (int j = 0; j < 4; ++j) sm.sA[tg * 4 + j][w] = ds[j];
    __syncthreads();
    {
        float d = sm.sA[w][l & 15];
        #pragma unroll
        for (int off = 8; off; off >>= 1)
            d += __shfl_xor_sync(0xffffffffu, d, off);
        if (l == 0) sm.sInv[w] = 1.0f / d;
    }
    __syncthreads();

    float inv[4];
    #pragma unroll
    for (int j = 0; j < 4; ++j) inv[j] = sm.sInv[tg * 4 + j];
    #pragma unroll
    for (int i = 0; i < 8; ++i) {
        float t = fmaf(v[i].x, inv[0], a[i]);
        t = fmaf(v[i].y, inv[1], t);
        t = fmaf(v[i].z, inv[2], t);
        a[i] = fmaf(v[i].w, inv[3], t);
    }
}

__global__ void __launch_bounds__(THREADS, 1)
attn_main(const float* __restrict__ dh, const float* __restrict__ enc) {
    __shared__ Smem sm;

    const int tid = threadIdx.x;
    const int w   = tid >> 5;
    const int l   = tid & 31;
    const int tg  = l & 3;              // t-quad within warp
    const int hcw = l >> 2;             // h-chunk within warp (0..7)
    const int h0  = (w * 8 + hcw) * 8;  // this thread's 8 consecutive h

    float4 vA[8], vB[8];
    float4 dh4a, dh4b;

    int p = blockIdx.x;                 // pair id, strided by GRID
    // prologue: prefetch first tile + this pair's dh slice
    issue_tile(vA, enc, p, 0, h0, tg);
    dh4a = __ldg(reinterpret_cast<const float4*>(dh + (p >> 5) * HS + h0));
    dh4b = __ldg(reinterpret_cast<const float4*>(dh + (p >> 5) * HS + h0 + 4));

    for (; p < NPAIRS; p += GRID) {
        float dhv[8] = {dh4a.x, dh4a.y, dh4a.z, dh4a.w,
                        dh4b.x, dh4b.y, dh4b.z, dh4b.w};
        float a[8] = {0.f, 0.f, 0.f, 0.f, 0.f, 0.f, 0.f, 0.f};

        // process tile (p,0) while tile (p,1) streams
        issue_tile(vB, enc, p, 1, h0, tg);
        process_tile(vA, dhv, a, sm, w, l, tg, hcw);

        // prefetch next pair's tile 0 + dh while tile (p,1) is processed
        const int pn = p + GRID;
        if (pn < NPAIRS) {
            issue_tile(vA, enc, pn, 0, h0, tg);
            dh4a = __ldg(reinterpret_cast<const float4*>(dh + (pn >> 5) * HS + h0));
            dh4b = __ldg(reinterpret_cast<const float4*>(dh + (pn >> 5) * HS + h0 + 4));
        }
        process_tile(vB, dhv, a, sm, w, l, tg, hcw);

        // flush pair accumulator: sum across the 4 tg lanes, write 8 floats
        #pragma unroll
        for (int off = 1; off <= 2; off <<= 1)
            #pragma unroll
            for (int i = 0; i < 8; ++i)
                a[i] += __shfl_xor_sync(0xffffffffu, a[i], off);
        if (tg == 0) {
            float* pr = g_partial + (size_t)p * HS + h0;
            float4 o0 = {a[0], a[1], a[2], a[3]};
            float4 o1 = {a[4], a[5], a[6], a[7]};
            *reinterpret_cast<float4*>(pr)     = o0;
            *reinterpret_cast<float4*>(pr + 4) = o1;
        }
    }
}

// out[b,h] = sum over the 32 pairs of b (deterministic order), float4-wide.
// 128 blocks x 128 threads = 16384 threads = one float4 each.
__global__ void __launch_bounds__(128)
attn_reduce(float* __restrict__ out) {
    const int idx = blockIdx.x * 128 + threadIdx.x;   // 0..16383
    const int b   = idx >> 8;                         // 256 float4 per b
    const int q   = idx & 255;
    const float4* p = reinterpret_cast<const float4*>(g_partial)
                    + (size_t)b * 32 * (HS / 4) + q;
    float4 acc = {0.f, 0.f, 0.f, 0.f};
    #pragma unroll
    for (int k = 0; k < 32; ++k) {
        const float4 x = __ldg(p + (size_t)k * (HS / 4));
        acc.x += x.x; acc.y += x.y; acc.z += x.z; acc.w += x.w;
    }
    reinterpret_cast<float4*>(out)[idx] = acc;
}

extern "C" void kernel_launch(void* const* d_in, const int* in_sizes, int n_in,
                              void* d_out, int out_size) {
    const float* dh  = (const float*)d_in[0];
    const float* enc = (const float*)d_in[1];
    if (n_in >= 2 && in_sizes[0] > in_sizes[1]) {
        enc = (const float*)d_in[0];
        dh  = (const float*)d_in[1];
    }
    float* out = (float*)d_out;

    attn_main<<<GRID, THREADS>>>(dh, enc);
    attn_reduce<<<128, 128>>>(out);
}

// round 5
// speedup vs baseline: 1.4032x; 1.4032x over previous
#include <cuda_runtime.h>
#include <math.h>
#include <stdint.h>

// Fixed shape: H=1024, B=64, T=1024
#define BB 64
#define TS 1024
#define HS 1024
#define TT 16                         // t per tile
#define GRID 128
#define CHUNK 32                      // tiles per CTA (fixed b per CTA)
#define DEPTH 3
#define TILE_FLOATS (HS * TT)         // 16384
#define TILE_BYTES  (TILE_FLOATS * 4) // 64 KB
#define HSTRIDE ((size_t)BB * TS)     // floats between consecutive h
#define SMEM_BYTES (DEPTH * TILE_BYTES + 64 + 4096)

// per-CTA partials: [GRID][HS] = 512 KB
__device__ float g_partial[GRID * HS];

// ---------- PTX helpers ----------
__device__ __forceinline__ uint32_t smem_u32(const void* p) {
    return (uint32_t)__cvta_generic_to_shared(p);
}
__device__ __forceinline__ void mbar_init(uint32_t a, uint32_t cnt) {
    asm volatile("mbarrier.init.shared.b64 [%0], %1;" :: "r"(a), "r"(cnt) : "memory");
}
__device__ __forceinline__ void mbar_arrive(uint32_t a) {
    asm volatile("mbarrier.arrive.shared.b64 _, [%0];" :: "r"(a) : "memory");
}
#define MB_WAIT(addr, parity) do {                                              \
    uint32_t _m = (addr); uint32_t _p = (parity); uint32_t _d;                  \
    asm volatile("{\n\t.reg .pred p;\n\t"                                       \
        "mbarrier.try_wait.parity.acquire.cta.shared::cta.b64 p, [%1], %2;\n\t" \
        "selp.b32 %0, 1, 0, p;\n\t}"                                            \
        : "=r"(_d) : "r"(_m), "r"(_p) : "memory");                              \
    if (!_d) {                                                                  \
        asm volatile("{\n\t.reg .pred P1;\n\t"                                  \
            "W%=:\n\t"                                                          \
            "mbarrier.try_wait.parity.acquire.cta.shared::cta.b64 P1, [%0], %1, 0x989680;\n\t" \
            "@P1 bra.uni D%=;\n\t"                                              \
            "bra.uni W%=;\n\t"                                                  \
            "D%=:\n\t}" :: "r"(_m), "r"(_p) : "memory");                        \
    }                                                                           \
} while (0)

__device__ __forceinline__ void cp16(uint32_t dst, const float* src) {
    asm volatile("cp.async.cg.shared.global [%0], [%1], 16;" :: "r"(dst), "l"(src));
}

// smem layout: [0, DEPTH*TILE_BYTES) ring | 64B mbarriers | 4KB sred
// sred: sA [2][8][16] @ 0 | sB @ 256 | sC @ 512 | sD @ 768  (floats)

__global__ void __launch_bounds__(384, 1)
attn_main(const float* __restrict__ dh, const float* __restrict__ enc) {
    extern __shared__ float smem_dyn[];
    float* ring = smem_dyn;
    const uint32_t sbase = smem_u32(smem_dyn);
    const uint32_t mb = sbase + DEPTH * TILE_BYTES;  // full(s)=mb+s*16, empty=+8
    float* sred = smem_dyn + DEPTH * TILE_FLOATS + 16;

    const int tid = threadIdx.x;
    const int w = tid >> 5, l = tid & 31;
    const int b = blockIdx.x >> 1;           // 2 CTAs per batch row
    const int tile0 = blockIdx.x * CHUNK;

    if (tid == 0) {
        #pragma unroll
        for (int s = 0; s < DEPTH; ++s) {
            mbar_init(mb + s * 16, 128);      // full: 128 producer threads
            mbar_init(mb + s * 16 + 8, 256);  // empty: 256 consumer threads
        }
    }
    __syncthreads();

    if (w >= 8) {
        // ---------------- producers (warps 8..11) ----------------
        const int pw = w - 8;
        const int c = l & 3, r = l >> 2;          // 4 lanes per 64B row
        const float* gbase = enc + (size_t)(pw * 8 + r) * HSTRIDE
                                 + (size_t)b * TS + c * 4;
        const uint32_t sm0 = sbase + (uint32_t)((pw * 8 + r) * (TT * 4) + c * 16);

        for (int n = 0; n < CHUNK; ++n) {
            const int s = n % DEPTH;
            if (n >= DEPTH)
                MB_WAIT(mb + s * 16 + 8, ((n / DEPTH) & 1) ^ 1);
            const int t0 = ((tile0 + n) & 63) * TT;
            const float* g = gbase + t0;
            const uint32_t d0 = sm0 + (uint32_t)s * TILE_BYTES;
            #pragma unroll
            for (int i = 0; i < 32; ++i)
                cp16(d0 + (uint32_t)i * 32 * (TT * 4), g + (size_t)i * 32 * HSTRIDE);
            asm volatile("cp.async.commit_group;" ::: "memory");
            if (n >= 1) {
                asm volatile("cp.async.wait_group 1;" ::: "memory");
                mbar_arrive(mb + ((n - 1) % DEPTH) * 16);
            }
        }
        asm volatile("cp.async.wait_group 0;" ::: "memory");
        mbar_arrive(mb + ((CHUNK - 1) % DEPTH) * 16);
    } else {
        // ---------------- consumers (warps 0..7) ----------------
        const int cw = w, tq = l & 3, hr = l >> 2;
        const int rbase = cw * 8 + hr;            // rows rbase + 64*i

        float dhv[16];
        #pragma unroll
        for (int i = 0; i < 16; ++i)
            dhv[i] = __ldg(dh + b * HS + rbase + 64 * i);

        float acc[16];
        #pragma unroll
        for (int i = 0; i < 16; ++i) acc[i] = 0.0f;

        for (int n = 0; n < CHUNK; ++n) {
            const int s = n % DEPTH;
            const int ph = (n / DEPTH) & 1;
            const int pr = (n & 1) * 128;          // sred parity slice

            MB_WAIT(mb + s * 16, ph);

            // tile slice -> registers (16 x LDS.128, conflict-free)
            float4 v[16];
            const float* tp = ring + (size_t)s * TILE_FLOATS + rbase * TT + tq * 4;
            #pragma unroll
            for (int i = 0; i < 16; ++i)
                v[i] = *reinterpret_cast<const float4*>(tp + i * 64 * TT);

            // stats partials over this thread's 16 h-rows
            float4 sp = {0.f, 0.f, 0.f, 0.f};
            float4 mx = {-INFINITY, -INFINITY, -INFINITY, -INFINITY};
            float4 mn = { INFINITY,  INFINITY,  INFINITY,  INFINITY};
            #pragma unroll
            for (int i = 0; i < 16; ++i) {
                sp.x = fmaf(v[i].x, dhv[i], sp.x); sp.y = fmaf(v[i].y, dhv[i], sp.y);
                sp.z = fmaf(v[i].z, dhv[i], sp.z); sp.w = fmaf(v[i].w, dhv[i], sp.w);
                mx.x = fmaxf(mx.x, v[i].x); mx.y = fmaxf(mx.y, v[i].y);
                mx.z = fmaxf(mx.z, v[i].z); mx.w = fmaxf(mx.w, v[i].w);
                mn.x = fminf(mn.x, v[i].x); mn.y = fminf(mn.y, v[i].y);
                mn.z = fminf(mn.z, v[i].z); mn.w = fminf(mn.w, v[i].w);
            }
            #pragma unroll
            for (int off = 4; off <= 16; off <<= 1) {
                sp.x += __shfl_xor_sync(~0u, sp.x, off); sp.y += __shfl_xor_sync(~0u, sp.y, off);
                sp.z += __shfl_xor_sync(~0u, sp.z, off); sp.w += __shfl_xor_sync(~0u, sp.w, off);
                mx.x = fmaxf(mx.x, __shfl_xor_sync(~0u, mx.x, off));
                mx.y = fmaxf(mx.y, __shfl_xor_sync(~0u, mx.y, off));
                mx.z = fmaxf(mx.z, __shfl_xor_sync(~0u, mx.z, off));
                mx.w = fmaxf(mx.w, __shfl_xor_sync(~0u, mx.w, off));
                mn.x = fminf(mn.x, __shfl_xor_sync(~0u, mn.x, off));
                mn.y = fminf(mn.y, __shfl_xor_sync(~0u, mn.y, off));
                mn.z = fminf(mn.z, __shfl_xor_sync(~0u, mn.z, off));
                mn.w = fminf(mn.w, __shfl_xor_sync(~0u, mn.w, off));
            }
            // tile fully in registers -> release the smem buffer
            mbar_arrive(mb + s * 16 + 8);

            if (hr == 0) {   // lanes 0..3 hold per-(cw, t) partials
                float* pA = sred + pr + cw * 16 + tq * 4;
                pA[0] = sp.x; pA[1] = sp.y; pA[2] = sp.z; pA[3] = sp.w;
                float* pB = pA + 256;
                pB[0] = mx.x; pB[1] = mx.y; pB[2] = mx.z; pB[3] = mx.w;
                float* pC = pA + 512;
                pC[0] = mn.x; pC[1] = mn.y; pC[2] = mn.z; pC[3] = mn.w;
            }
            asm volatile("bar.sync 1, 256;" ::: "memory");

            // per-t combine (redundant per thread for its 4 t's)
            float st[4], Mt[4];
            #pragma unroll
            for (int j = 0; j < 4; ++j) {
                const int t = tq * 4 + j;
                float s_ = 0.f, X = -INFINITY, N = INFINITY;
                #pragma unroll
                for (int c2 = 0; c2 < 8; ++c2) {
                    s_ += sred[pr + c2 * 16 + t];
                    X = fmaxf(X, sred[256 + pr + c2 * 16 + t]);
                    N = fminf(N, sred[512 + pr + c2 * 16 + t]);
                }
                st[j] = s_;
                Mt[j] = (s_ >= 0.f) ? X * s_ : N * s_;   // exact max_h(v*s)
            }

            // exp on registers + denominator partials
            float4 ds = {0.f, 0.f, 0.f, 0.f};
            #pragma unroll
            for (int i = 0; i < 16; ++i) {
                v[i].x = __expf(fmaf(v[i].x, st[0], -Mt[0])); ds.x += v[i].x;
                v[i].y = __expf(fmaf(v[i].y, st[1], -Mt[1])); ds.y += v[i].y;
                v[i].z = __expf(fmaf(v[i].z, st[2], -Mt[2])); ds.z += v[i].z;
                v[i].w = __expf(fmaf(v[i].w, st[3], -Mt[3])); ds.w += v[i].w;
            }
            #pragma unroll
            for (int off = 4; off <= 16; off <<= 1) {
                ds.x += __shfl_xor_sync(~0u, ds.x, off);
                ds.y += __shfl_xor_sync(~0u, ds.y, off);
                ds.z += __shfl_xor_sync(~0u, ds.z, off);
                ds.w += __shfl_xor_sync(~0u, ds.w, off);
            }
            if (hr == 0) {
                float* pD = sred + 768 + pr + cw * 16 + tq * 4;
                pD[0] = ds.x; pD[1] = ds.y; pD[2] = ds.z; pD[3] = ds.w;
            }
            asm volatile("bar.sync 1, 256;" ::: "memory");

            float inv[4];
            #pragma unroll
            for (int j = 0; j < 4; ++j) {
                float d = 0.f;
                #pragma unroll
                for (int c2 = 0; c2 < 8; ++c2)
                    d += sred[768 + pr + c2 * 16 + tq * 4 + j];
                inv[j] = 1.0f / d;
            }
            #pragma unroll
            for (int i = 0; i < 16; ++i) {
                float a = v[i].x * inv[0];
                a = fmaf(v[i].y, inv[1], a);
                a = fmaf(v[i].z, inv[2], a);
                a = fmaf(v[i].w, inv[3], a);
                acc[i] += a;
            }
        }

        // flush: sum across the 4 tq lanes, write this CTA's per-h partials
        #pragma unroll
        for (int i = 0; i < 16; ++i) {
            acc[i] += __shfl_xor_sync(~0u, acc[i], 1);
            acc[i] += __shfl_xor_sync(~0u, acc[i], 2);
        }
        if (tq == 0) {
            float* p = g_partial + (size_t)blockIdx.x * HS + rbase;
            #pragma unroll
            for (int i = 0; i < 16; ++i) p[64 * i] = acc[i];
        }
    }
}

// out[b,h] = partial[2b][h] + partial[2b+1][h]
__global__ void __launch_bounds__(256)
attn_reduce(float* __restrict__ out) {
    const int idx = blockIdx.x * 256 + threadIdx.x;  // 0..16383 (float4 units)
    const int bb = idx >> 8, q = idx & 255;
    const float4* p = reinterpret_cast<const float4*>(g_partial);
    const float4 a = p[(2 * bb) * 256 + q];
    const float4 c = p[(2 * bb + 1) * 256 + q];
    float4 o = {a.x + c.x, a.y + c.y, a.z + c.z, a.w + c.w};
    reinterpret_cast<float4*>(out)[idx] = o;
}

extern "C" void kernel_launch(void* const* d_in, const int* in_sizes, int n_in,
                              void* d_out, int out_size) {
    const float* dh  = (const float*)d_in[0];
    const float* enc = (const float*)d_in[1];
    if (n_in >= 2 && in_sizes[0] > in_sizes[1]) {
        enc = (const float*)d_in[0];
        dh  = (const float*)d_in[1];
    }
    float* out = (float*)d_out;

    cudaFuncSetAttribute(attn_main,
                         cudaFuncAttributeMaxDynamicSharedMemorySize, SMEM_BYTES);
    attn_main<<<GRID, 384, SMEM_BYTES>>>(dh, enc);
    attn_reduce<<<64, 256>>>(out);
}